// round 3
// baseline (speedup 1.0000x reference)
#include <cuda_runtime.h>

typedef unsigned long long u64;

#define H       128
#define SEQ     1024
#define MBLK    4
#define NCTAS   128
#define NTHR    512
#define COUT    10

#define NGROUPS 8           // 4-k groups per thread (32 k's per kq quarter)
#define REG_G   2           // groups with register-resident weights
#define SMEM_G  (NGROUPS - REG_G)   // 6 groups from smem

#define XSTRIDE 1032        // padded floats per x row (bank-spread for kq reads)

// ---- dynamic smem layout (bytes, 16B aligned) ----
#define WS_OFF    0
#define WS_BYTES  (SMEM_G * 4 * 512 * 16)       // 196608: ulonglong2 [ (sg*4+q) ][ n*4+kq ]
#define XS_OFF    (WS_OFF + WS_BYTES)
#define XS_BYTES  (MBLK * XSTRIDE * 4)          // 16512
#define WPS_OFF   (XS_OFF + XS_BYTES)
#define WPS_BYTES (H * COUT * 4)                // 5120
#define HB_OFF    (WPS_OFF + WPS_BYTES)
#define HB_BYTES  (2 * MBLK * 512)              // 4096: double-buffered swizzled h
#define SMEM_TOTAL (HB_OFF + HB_BYTES)          // 222336 <= 232448

__device__ __forceinline__ u64 pk2(float lo, float hi) {
    u64 r;
    asm("mov.b64 %0, {%1, %2};" : "=l"(r) : "f"(lo), "f"(hi));
    return r;
}
__device__ __forceinline__ void upk2(u64 v, float& lo, float& hi) {
    asm("mov.b64 {%0, %1}, %2;" : "=f"(lo), "=f"(hi) : "l"(v));
}
__device__ __forceinline__ u64 ffma2(u64 a, u64 b, u64 c) {
    u64 d;
    asm("fma.rn.f32x2 %0, %1, %2, %3;" : "=l"(d) : "l"(a), "l"(b), "l"(c));
    return d;
}

// Overflow-safe fast tanh / sigmoid (validated rel_err ~3e-7 in R1/R2).
__device__ __forceinline__ float tanh_fast(float x) {
    float a = fabsf(x);
    float e = __expf(2.0f * a);
    float r = 1.0f - __fdividef(2.0f, e + 1.0f);
    return copysignf(r, x);
}
__device__ __forceinline__ float sigmoid_fast(float x) {
    float e = __expf(-x);
    return __fdividef(1.0f, 1.0f + e);
}

// h swizzle: k = kqk*32 + g*4 + e  ->  byte offset within a 512B row:
//   slot s = kqk*8 + ((g + kqk) & 7),  off = s*16 + e*4
__device__ __forceinline__ int h_swz_off(int k) {
    int kqk = k >> 5, g = (k >> 2) & 7, e = k & 3;
    int s = kqk * 8 + ((g + kqk) & 7);
    return s * 16 + e * 4;
}

__global__ void __launch_bounds__(NTHR, 1)
lstm_persistent_kernel(const float* __restrict__ x,
                       const float* __restrict__ Wgx, const float* __restrict__ Wgh, const float* __restrict__ bg,
                       const float* __restrict__ Wix, const float* __restrict__ Wih, const float* __restrict__ bi,
                       const float* __restrict__ Wfx, const float* __restrict__ Wfh, const float* __restrict__ bf,
                       const float* __restrict__ Wox, const float* __restrict__ Woh, const float* __restrict__ bo,
                       const float* __restrict__ Wph, const float* __restrict__ bp,
                       float* __restrict__ out)
{
    extern __shared__ char smem[];
    ulonglong2* ws = (ulonglong2*)(smem + WS_OFF);
    float*     xsm = (float*)(smem + XS_OFF);
    float*     wps = (float*)(smem + WPS_OFF);

    const int tid = threadIdx.x;
    const int kq  = tid & 3;        // k quarter: k in [kq*32, kq*32+32)
    const int n   = tid >> 2;       // gate column (owns cols n, H+n, 2H+n, 3H+n)
    const int m0  = blockIdx.x * MBLK;

    // ---- init smem weights: groups g = REG_G..7 for every (n, kq) ----
    // ws[(sg*4+q)*512 + nn*4+kqq]:
    //   q0={g,i} pair0  q1={f,o} pair0  q2={g,i} pair1  q3={f,o} pair1
    for (int i = tid; i < SMEM_G * 512; i += NTHR) {
        int sg  = i >> 9;
        int idx = i & 511;
        int nn  = idx >> 2, kqq = idx & 3;
        int k0  = kqq * 32 + (REG_G + sg) * 4;
        ulonglong2 v;
        v.x = pk2(Wgh[(k0+0)*H+nn], Wgh[(k0+1)*H+nn]);
        v.y = pk2(Wih[(k0+0)*H+nn], Wih[(k0+1)*H+nn]);
        ws[(sg*4+0)*512 + idx] = v;
        v.x = pk2(Wfh[(k0+0)*H+nn], Wfh[(k0+1)*H+nn]);
        v.y = pk2(Woh[(k0+0)*H+nn], Woh[(k0+1)*H+nn]);
        ws[(sg*4+1)*512 + idx] = v;
        v.x = pk2(Wgh[(k0+2)*H+nn], Wgh[(k0+3)*H+nn]);
        v.y = pk2(Wih[(k0+2)*H+nn], Wih[(k0+3)*H+nn]);
        ws[(sg*4+2)*512 + idx] = v;
        v.x = pk2(Wfh[(k0+2)*H+nn], Wfh[(k0+3)*H+nn]);
        v.y = pk2(Woh[(k0+2)*H+nn], Woh[(k0+3)*H+nn]);
        ws[(sg*4+3)*512 + idx] = v;
    }

    // ---- register weights for g = 0..REG_G-1 ----
    // wreg[g][0..7] = {g_p0, i_p0, f_p0, o_p0, g_p1, i_p1, f_p1, o_p1}
    u64 wreg[REG_G][8];
#pragma unroll
    for (int g = 0; g < REG_G; g++) {
        int k0 = kq * 32 + g * 4;
        wreg[g][0] = pk2(Wgh[(k0+0)*H+n], Wgh[(k0+1)*H+n]);
        wreg[g][1] = pk2(Wih[(k0+0)*H+n], Wih[(k0+1)*H+n]);
        wreg[g][2] = pk2(Wfh[(k0+0)*H+n], Wfh[(k0+1)*H+n]);
        wreg[g][3] = pk2(Woh[(k0+0)*H+n], Woh[(k0+1)*H+n]);
        wreg[g][4] = pk2(Wgh[(k0+2)*H+n], Wgh[(k0+3)*H+n]);
        wreg[g][5] = pk2(Wih[(k0+2)*H+n], Wih[(k0+3)*H+n]);
        wreg[g][6] = pk2(Wfh[(k0+2)*H+n], Wfh[(k0+3)*H+n]);
        wreg[g][7] = pk2(Woh[(k0+2)*H+n], Woh[(k0+3)*H+n]);
    }

    // ---- per-thread gate params: this thread owns row m = kq, column n ----
    const float wxg = Wgx[n], wxi = Wix[n], wxf = Wfx[n], wxo = Wox[n];
    const float bG = bg[(m0+kq)*H+n], bI = bi[(m0+kq)*H+n];
    const float bF = bf[(m0+kq)*H+n], bO = bo[(m0+kq)*H+n];

    // h-load slot byte offsets (per group), and h-store offset (k = n, row kq)
    int sloff[NGROUPS];
#pragma unroll
    for (int g = 0; g < NGROUPS; g++)
        sloff[g] = (kq * 8 + ((g + kq) & 7)) * 16;
    const int woff = kq * 512 + h_swz_off(n);

    // ---- preload x, Wph, zero h buffers ----
    for (int i = tid; i < MBLK * SEQ; i += NTHR) {
        int mm = i >> 10, tt = i & (SEQ - 1);
        xsm[mm * XSTRIDE + tt] = x[(m0+mm)*SEQ + tt];
    }
    for (int i = tid; i < H * COUT; i += NTHR) wps[i] = Wph[i];
    for (int i = tid; i < HB_BYTES / 4; i += NTHR)
        ((float*)(smem + HB_OFF))[i] = 0.0f;
    float c = 0.0f;
    __syncthreads();

    const char* wbase = (const char*)ws + (((unsigned)n * 4 + kq) * 16);
    const bool b0 = (kq & 1) != 0;
    const bool b1 = (kq & 2) != 0;

    // ---- time loop: ONE barrier per step (double-buffered h) ----
    for (int t = 0; t < SEQ; t++) {
        const char* hb = smem + HB_OFF + ((t & 1) ? MBLK * 512 : 0);
        char*       hw = smem + HB_OFF + ((t & 1) ? 0 : MBLK * 512);

        u64 acc[4][4];
#pragma unroll
        for (int gg = 0; gg < 4; gg++)
#pragma unroll
            for (int m = 0; m < 4; m++) acc[gg][m] = 0ull;

#pragma unroll
        for (int g = 0; g < NGROUPS; g++) {
            u64 wp0, wp1, wp2, wp3, wp4, wp5, wp6, wp7;
            if (g < REG_G) {
                wp0 = wreg[g][0]; wp1 = wreg[g][1]; wp2 = wreg[g][2]; wp3 = wreg[g][3];
                wp4 = wreg[g][4]; wp5 = wreg[g][5]; wp6 = wreg[g][6]; wp7 = wreg[g][7];
            } else {
                int sg = g - REG_G;
                ulonglong2 a0 = *(const ulonglong2*)(wbase + (sg*4+0) * 512 * 16);
                ulonglong2 a1 = *(const ulonglong2*)(wbase + (sg*4+1) * 512 * 16);
                ulonglong2 a2 = *(const ulonglong2*)(wbase + (sg*4+2) * 512 * 16);
                ulonglong2 a3 = *(const ulonglong2*)(wbase + (sg*4+3) * 512 * 16);
                wp0 = a0.x; wp1 = a0.y; wp2 = a1.x; wp3 = a1.y;
                wp4 = a2.x; wp5 = a2.y; wp6 = a3.x; wp7 = a3.y;
            }
#pragma unroll
            for (int m = 0; m < 4; m++) {
                ulonglong2 hu = *(const ulonglong2*)(hb + m * 512 + sloff[g]);
                acc[0][m] = ffma2(hu.x, wp0, acc[0][m]);
                acc[1][m] = ffma2(hu.x, wp1, acc[1][m]);
                acc[2][m] = ffma2(hu.x, wp2, acc[2][m]);
                acc[3][m] = ffma2(hu.x, wp3, acc[3][m]);
                acc[0][m] = ffma2(hu.y, wp4, acc[0][m]);
                acc[1][m] = ffma2(hu.y, wp5, acc[1][m]);
                acc[2][m] = ffma2(hu.y, wp6, acc[2][m]);
                acc[3][m] = ffma2(hu.y, wp7, acc[3][m]);
            }
        }

        // collapse f32x2 pairs -> p[gate][m]
        float p[4][4];
#pragma unroll
        for (int gg = 0; gg < 4; gg++)
#pragma unroll
            for (int m = 0; m < 4; m++) {
                float lo, hi;
                upk2(acc[gg][m], lo, hi);
                p[gg][m] = lo + hi;
            }

        // butterfly reduce across the 4 kq lanes -> z[gate] for row m = kq
        float z[4];
#pragma unroll
        for (int gg = 0; gg < 4; gg++) {
            float t0 = __shfl_xor_sync(0xFFFFFFFFu, b0 ? p[gg][0] : p[gg][1], 1);
            float qlo = (b0 ? p[gg][1] : p[gg][0]) + t0;          // row b0, kq-pair sum
            float t1 = __shfl_xor_sync(0xFFFFFFFFu, b0 ? p[gg][2] : p[gg][3], 1);
            float qhi = (b0 ? p[gg][3] : p[gg][2]) + t1;          // row 2+b0
            float t2 = __shfl_xor_sync(0xFFFFFFFFu, b1 ? qlo : qhi, 2);
            z[gg] = (b1 ? qhi : qlo) + t2;                        // row kq, full sum
        }

        // gates + state update for row kq, column n
        {
            float xv = xsm[kq * XSTRIDE + t];
            float zg = z[0] + fmaf(xv, wxg, bG);
            float zi = z[1] + fmaf(xv, wxi, bI);
            float zf = z[2] + fmaf(xv, wxf, bF);
            float zo = z[3] + fmaf(xv, wxo, bO);
            float gg = tanh_fast(zg);
            float ii = sigmoid_fast(zi);
            float ff = sigmoid_fast(zf);
            float oo = sigmoid_fast(zo);
            c = fmaf(gg, ii, c * ff);
            *(float*)(hw + woff) = tanh_fast(c) * oo;
        }

        __syncthreads();   // new h visible; safe because next step reads hw, writes hb
    }

    // ---- final projection: h is in buffer 0 after SEQ (even) steps ----
    const float* hf = (const float*)(smem + HB_OFF);
    if (tid < MBLK * COUT) {
        int m = tid / COUT, cc = tid - m * COUT;
        float s = bp[(m0+m)*COUT + cc];
#pragma unroll 16
        for (int k = 0; k < H; k++) {
            float hk = *(const float*)((const char*)hf + m * 512 + h_swz_off(k));
            s = fmaf(hk, wps[k*COUT + cc], s);
        }
        out[(m0+m)*COUT + cc] = s;
    }
}

extern "C" void kernel_launch(void* const* d_in, const int* in_sizes, int n_in,
                              void* d_out, int out_size) {
    const float* x   = (const float*)d_in[0];
    const float* Wgx = (const float*)d_in[1];
    const float* Wgh = (const float*)d_in[2];
    const float* bg  = (const float*)d_in[3];
    const float* Wix = (const float*)d_in[4];
    const float* Wih = (const float*)d_in[5];
    const float* bi  = (const float*)d_in[6];
    const float* Wfx = (const float*)d_in[7];
    const float* Wfh = (const float*)d_in[8];
    const float* bf  = (const float*)d_in[9];
    const float* Wox = (const float*)d_in[10];
    const float* Woh = (const float*)d_in[11];
    const float* bo  = (const float*)d_in[12];
    const float* Wph = (const float*)d_in[13];
    const float* bp  = (const float*)d_in[14];
    float* out = (float*)d_out;

    cudaFuncSetAttribute(lstm_persistent_kernel,
                         cudaFuncAttributeMaxDynamicSharedMemorySize, SMEM_TOTAL);

    lstm_persistent_kernel<<<NCTAS, NTHR, SMEM_TOTAL>>>(
        x, Wgx, Wgh, bg, Wix, Wih, bi, Wfx, Wfh, bf, Wox, Woh, bo, Wph, bp, out);
}

// round 4
// speedup vs baseline: 1.0829x; 1.0829x over previous
#include <cuda_runtime.h>

typedef unsigned long long u64;

#define H       128
#define SEQ     1024
#define MBLK    4
#define NCTAS   128
#define NTHR    512
#define COUT    10

#define NGROUPS 16          // 4-k groups per kh half (64 k's per thread)
#define RG      9           // groups with register-resident weights
#define SG      (NGROUPS - RG)   // 7 groups from smem

#define PSTR    9           // pbuf floats per (m,n) cell: 8 data + 1 pad

// ---- dynamic smem layout (bytes, 16B aligned) ----
#define WS_OFF    0
#define WS_BYTES  (SG * 2 * NTHR * 16)          // 114688: ulonglong2 [sg*2+q][tid]
#define PB_OFF    (WS_OFF + WS_BYTES)
#define PB_BYTES  (4 * 128 * PSTR * 4)          // 18432
#define XS_OFF    (PB_OFF + PB_BYTES)
#define XS_BYTES  (MBLK * SEQ * 4)              // 16384
#define WPS_OFF   (XS_OFF + XS_BYTES)
#define WPS_BYTES (H * COUT * 4)                // 5120
#define HS_OFF    (WPS_OFF + WPS_BYTES)
#define HS_BYTES  (MBLK * H * 4)                // 2048
#define SMEM_TOTAL (HS_OFF + HS_BYTES)          // 156672

__device__ __forceinline__ u64 pk2(float lo, float hi) {
    u64 r;
    asm("mov.b64 %0, {%1, %2};" : "=l"(r) : "f"(lo), "f"(hi));
    return r;
}
__device__ __forceinline__ void upk2(u64 v, float& lo, float& hi) {
    asm("mov.b64 {%0, %1}, %2;" : "=f"(lo), "=f"(hi) : "l"(v));
}
__device__ __forceinline__ u64 ffma2(u64 a, u64 b, u64 c) {
    u64 d;
    asm("fma.rn.f32x2 %0, %1, %2, %3;" : "=l"(d) : "l"(a), "l"(b), "l"(c));
    return d;
}

// Overflow-safe fast tanh / sigmoid (validated rel_err ~3e-7 across R1-R3).
__device__ __forceinline__ float tanh_fast(float x) {
    float a = fabsf(x);
    float e = __expf(2.0f * a);
    float r = 1.0f - __fdividef(2.0f, e + 1.0f);
    return copysignf(r, x);
}
__device__ __forceinline__ float sigmoid_fast(float x) {
    float e = __expf(-x);
    return __fdividef(1.0f, 1.0f + e);
}

__global__ void __launch_bounds__(NTHR, 1)
lstm_persistent_kernel(const float* __restrict__ x,
                       const float* __restrict__ Wgx, const float* __restrict__ Wgh, const float* __restrict__ bg,
                       const float* __restrict__ Wix, const float* __restrict__ Wih, const float* __restrict__ bi,
                       const float* __restrict__ Wfx, const float* __restrict__ Wfh, const float* __restrict__ bf,
                       const float* __restrict__ Wox, const float* __restrict__ Woh, const float* __restrict__ bo,
                       const float* __restrict__ Wph, const float* __restrict__ bp,
                       float* __restrict__ out)
{
    extern __shared__ char smem[];
    ulonglong2* ws = (ulonglong2*)(smem + WS_OFF);
    float*    pbuf = (float*)(smem + PB_OFF);
    float*     xsm = (float*)(smem + XS_OFF);
    float*     wps = (float*)(smem + WPS_OFF);
    float*      hs = (float*)(smem + HS_OFF);   // [4][128] plain f32

    const int tid = threadIdx.x;
    const int n   = tid & 127;          // column within gate block
    const int s   = tid >> 7;           // split 0..3
    const int kh  = s & 1;              // k-half: [kh*64, kh*64+64)
    const int gh  = s >> 1;             // gate half: 0 -> (g,i), 1 -> (f,o)
    const int khbase = kh << 6;
    const int m0  = blockIdx.x * MBLK;

    // Gate-half weight matrices for this thread
    const float* WA = gh ? Wfh : Wgh;
    const float* WB = gh ? Woh : Wih;

    // ---- smem weights: groups RG..15 of this thread's (kh, gh, n) slice ----
    // ws[(sg*2+0)][tid] = {pk2(WA k0,k1), pk2(WB k0,k1)}
    // ws[(sg*2+1)][tid] = {pk2(WA k2,k3), pk2(WB k2,k3)}
#pragma unroll
    for (int sg = 0; sg < SG; sg++) {
        int k0 = khbase + (RG + sg) * 4;
        ulonglong2 v;
        v.x = pk2(WA[(k0+0)*H+n], WA[(k0+1)*H+n]);
        v.y = pk2(WB[(k0+0)*H+n], WB[(k0+1)*H+n]);
        ws[(sg*2+0)*NTHR + tid] = v;
        v.x = pk2(WA[(k0+2)*H+n], WA[(k0+3)*H+n]);
        v.y = pk2(WB[(k0+2)*H+n], WB[(k0+3)*H+n]);
        ws[(sg*2+1)*NTHR + tid] = v;
    }

    // ---- register weights: groups 0..RG-1 ----
    // wreg[g][0]={A_k0,A_k1} [1]={B_k0,B_k1} [2]={A_k2,A_k3} [3]={B_k2,B_k3}
    u64 wreg[RG][4];
#pragma unroll
    for (int g = 0; g < RG; g++) {
        int k0 = khbase + g * 4;
        wreg[g][0] = pk2(WA[(k0+0)*H+n], WA[(k0+1)*H+n]);
        wreg[g][1] = pk2(WB[(k0+0)*H+n], WB[(k0+1)*H+n]);
        wreg[g][2] = pk2(WA[(k0+2)*H+n], WA[(k0+3)*H+n]);
        wreg[g][3] = pk2(WB[(k0+2)*H+n], WB[(k0+3)*H+n]);
    }

    // ---- gate-phase params: this thread owns row m = s, column n ----
    const float wxg = Wgx[n], wxi = Wix[n], wxf = Wfx[n], wxo = Wox[n];
    const float bG = bg[(m0+s)*H+n], bI = bi[(m0+s)*H+n];
    const float bF = bf[(m0+s)*H+n], bO = bo[(m0+s)*H+n];

    // ---- preload x, Wph, zero h ----
    for (int i = tid; i < MBLK * SEQ; i += NTHR) {
        int mm = i >> 10, tt = i & (SEQ - 1);
        xsm[i] = x[(m0+mm)*SEQ + tt];
    }
    for (int i = tid; i < H * COUT; i += NTHR) wps[i] = Wph[i];
    for (int i = tid; i < MBLK * H; i += NTHR) hs[i] = 0.0f;
    float c = 0.0f;
    __syncthreads();

    // partial-buffer addresses
    float* pw = pbuf + (unsigned)n * PSTR + (gh << 2) + kh;    // + m*128*PSTR per row
    const float* pr = pbuf + ((unsigned)(s * 128 + n)) * PSTR; // reader: 8 floats

    // ---- time loop: 2 barriers per step ----
    for (int t = 0; t < SEQ; t++) {
        u64 accA[4], accB[4];
#pragma unroll
        for (int m = 0; m < 4; m++) { accA[m] = 0ull; accB[m] = 0ull; }

#pragma unroll
        for (int g = 0; g < NGROUPS; g++) {
            u64 wA0, wB0, wA1, wB1;
            if (g < RG) {
                wA0 = wreg[g][0]; wB0 = wreg[g][1];
                wA1 = wreg[g][2]; wB1 = wreg[g][3];
            } else {
                int sg = g - RG;
                ulonglong2 q0 = ws[(sg*2+0)*NTHR + tid];
                ulonglong2 q1 = ws[(sg*2+1)*NTHR + tid];
                wA0 = q0.x; wB0 = q0.y; wA1 = q1.x; wB1 = q1.y;
            }
            const float* hp = hs + khbase + (g << 2);
#pragma unroll
            for (int m = 0; m < 4; m++) {
                ulonglong2 hu = *(const ulonglong2*)(hp + (m << 7));  // broadcast
                accA[m] = ffma2(hu.x, wA0, accA[m]);
                accB[m] = ffma2(hu.x, wB0, accB[m]);
                accA[m] = ffma2(hu.y, wA1, accA[m]);
                accB[m] = ffma2(hu.y, wB1, accB[m]);
            }
        }

        // collapse f32x2 pairs, write 8 partials (conflict-free: stride PSTR=9)
#pragma unroll
        for (int m = 0; m < 4; m++) {
            float lo, hi;
            upk2(accA[m], lo, hi);
            pw[m * 128 * PSTR]     = lo + hi;
            upk2(accB[m], lo, hi);
            pw[m * 128 * PSTR + 2] = lo + hi;
        }
        __syncthreads();   // partials visible; all h reads of this step done

        // gate phase: thread owns (m = s, n). slots: gate*2 + kh
        {
            float xv = xsm[(s << 10) + t];
            float zg = pr[0] + pr[1] + fmaf(xv, wxg, bG);
            float zi = pr[2] + pr[3] + fmaf(xv, wxi, bI);
            float zf = pr[4] + pr[5] + fmaf(xv, wxf, bF);
            float zo = pr[6] + pr[7] + fmaf(xv, wxo, bO);
            float gg = tanh_fast(zg);
            float ii = sigmoid_fast(zi);
            float ff = sigmoid_fast(zf);
            float oo = sigmoid_fast(zo);
            c = fmaf(gg, ii, c * ff);
            hs[(s << 7) + n] = tanh_fast(c) * oo;
        }
        __syncthreads();   // new h visible
    }

    // ---- final projection: out = h @ Wph + bp ----
    if (tid < MBLK * COUT) {
        int m = tid / COUT, cc = tid - m * COUT;
        float ssum = bp[(m0+m)*COUT + cc];
#pragma unroll 16
        for (int k = 0; k < H; k++)
            ssum = fmaf(hs[(m << 7) + k], wps[k*COUT + cc], ssum);
        out[(m0+m)*COUT + cc] = ssum;
    }
}

extern "C" void kernel_launch(void* const* d_in, const int* in_sizes, int n_in,
                              void* d_out, int out_size) {
    const float* x   = (const float*)d_in[0];
    const float* Wgx = (const float*)d_in[1];
    const float* Wgh = (const float*)d_in[2];
    const float* bg  = (const float*)d_in[3];
    const float* Wix = (const float*)d_in[4];
    const float* Wih = (const float*)d_in[5];
    const float* bi  = (const float*)d_in[6];
    const float* Wfx = (const float*)d_in[7];
    const float* Wfh = (const float*)d_in[8];
    const float* bf  = (const float*)d_in[9];
    const float* Wox = (const float*)d_in[10];
    const float* Woh = (const float*)d_in[11];
    const float* bo  = (const float*)d_in[12];
    const float* Wph = (const float*)d_in[13];
    const float* bp  = (const float*)d_in[14];
    float* out = (float*)d_out;

    cudaFuncSetAttribute(lstm_persistent_kernel,
                         cudaFuncAttributeMaxDynamicSharedMemorySize, SMEM_TOTAL);

    lstm_persistent_kernel<<<NCTAS, NTHR, SMEM_TOTAL>>>(
        x, Wgx, Wgh, bg, Wix, Wih, bi, Wfx, Wfh, bf, Wox, Woh, bo, Wph, bp, out);
}